// round 1
// baseline (speedup 1.0000x reference)
#include <cuda_runtime.h>
#include <cstdint>

// Problem constants
#define B_   128
#define T_   512
#define D_   256
#define H_   512
#define G_   2048          // 4*H
#define K0_  768           // D + H (layer0 concat K)
#define K1_  1024          // H + H (layer1 concat K)
#define MT   64            // batch tile
#define NT   64            // gate-col tile (16 h-cols x 4 gates)
#define KS   32            // k slice
#define NCTA 128
#define L0_CTAS 64
#define BH   (B_ * H_)

// ---------------- persistent device scratch (no allocations allowed) ---------
__device__ float g_W0T[(size_t)K0_ * G_];   // [k][n'] k-major, gate-interleaved, proj folded (6 MB)
__device__ float g_W1T[(size_t)K1_ * G_];   // [k][n'] (8 MB)
__device__ float g_b0[G_];
__device__ float g_b1[G_];
// state: [0]=h0 buf0 [BH]=h0 buf1 [2BH]=h1 buf0 [3BH]=h1 buf1 [4BH]=c0 [5BH]=c1
__device__ float g_state[6 * BH];
__device__ unsigned g_count;
__device__ unsigned g_release;

// ---------------- helpers ----------------------------------------------------
__device__ __forceinline__ unsigned long long packdup(float w) {
    unsigned long long r;
    unsigned u = __float_as_uint(w);
    asm("mov.b64 %0, {%1, %1};" : "=l"(r) : "r"(u));
    return r;
}
__device__ __forceinline__ void ffma2(unsigned long long& d,
                                      unsigned long long a,
                                      unsigned long long b) {
    asm("fma.rn.f32x2 %0, %1, %2, %0;" : "+l"(d) : "l"(a), "l"(b));
}
__device__ __forceinline__ float2 unpack2(unsigned long long v) {
    unsigned lo, hi;
    asm("mov.b64 {%0, %1}, %2;" : "=r"(lo), "=r"(hi) : "l"(v));
    return make_float2(__uint_as_float(lo), __uint_as_float(hi));
}
__device__ __forceinline__ float sigm(float v) { return 1.f / (1.f + __expf(-v)); }

__device__ __forceinline__ void gridBarrier(unsigned target) {
    __syncthreads();
    if (threadIdx.x == 0) {
        __threadfence();
        unsigned t = atomicAdd(&g_count, 1u);
        if (t == (unsigned)(NCTA - 1)) {
            g_count = 0;
            __threadfence();
            atomicAdd(&g_release, 1u);
        } else {
            while ((int)(*(volatile unsigned*)&g_release - target) < 0) {}
        }
        __threadfence();
    }
    __syncthreads();
}

// ---------------- weight preparation -----------------------------------------
// W0T[d][n'] = sum_j wx0[n][j]*proj_w[j][d]   (proj folded in), d < 256
// b0[n']    = bx0[n] + bh0[n] + sum_j wx0[n][j]*proj_b[j]
// n' = jcol*4 + gate ; n = gate*H + jcol   (gate order i,f,g,o)
__global__ void prep_w0(const float* __restrict__ wx0, const float* __restrict__ projw,
                        const float* __restrict__ projb, const float* __restrict__ bx0,
                        const float* __restrict__ bh0) {
    int np = blockIdx.x;                 // n'
    int jcol = np >> 2, q = np & 3;
    int n = q * H_ + jcol;
    int d = threadIdx.x;                 // 0..255
    const float* wrow = wx0 + (size_t)n * D_;
    float acc = 0.f;
    for (int j = 0; j < D_; ++j) acc += wrow[j] * projw[(size_t)j * D_ + d];
    g_W0T[(size_t)d * G_ + np] = acc;
    if (d == 0) {
        float bb = bx0[n] + bh0[n];
        for (int j = 0; j < D_; ++j) bb += wrow[j] * projb[j];
        g_b0[np] = bb;
    }
}

// copies: W0T rows [256,768) = wh0 ; W1T = [wx1|wh1] ; b1 = bx1+bh1 (reordered)
__global__ void prep_copy(const float* __restrict__ wh0, const float* __restrict__ wx1,
                          const float* __restrict__ wh1, const float* __restrict__ bx1,
                          const float* __restrict__ bh1) {
    const int total = H_ * G_ + K1_ * G_ + G_;
    for (int i = blockIdx.x * blockDim.x + threadIdx.x; i < total;
         i += gridDim.x * blockDim.x) {
        if (i < H_ * G_) {
            int k = i / G_, np = i % G_;
            int n = (np & 3) * H_ + (np >> 2);
            g_W0T[(size_t)(D_ + k) * G_ + np] = wh0[(size_t)n * H_ + k];
        } else if (i < H_ * G_ + K1_ * G_) {
            int r = i - H_ * G_;
            int k = r / G_, np = r % G_;
            int n = (np & 3) * H_ + (np >> 2);
            float v = (k < H_) ? wx1[(size_t)n * H_ + k] : wh1[(size_t)n * H_ + (k - H_)];
            g_W1T[(size_t)k * G_ + np] = v;
        } else {
            int np = i - H_ * G_ - K1_ * G_;
            int n = (np & 3) * H_ + (np >> 2);
            g_b1[np] = bx1[n] + bh1[n];
        }
    }
}

// ---------------- fused GEMM tile + LSTM cell epilogue -----------------------
// Computes gates tile [MT batch x NT gate-cols] = concat(src1,src2) @ Wt + bias,
// then does the LSTM cell update for its (batch-rows x 16 h-cols) slice.
template <int KSZ, int LEN1>
__device__ __forceinline__ void lstm_tile(
    const float* __restrict__ Wt, const float* __restrict__ bias,
    const float* __restrict__ src1, int rs1,          // first concat source (row stride rs1)
    const float* __restrict__ src2,                   // second source (row stride H)
    float* __restrict__ cSt, float* __restrict__ hOut,
    int bBase, int n0, int jcol0,
    float* sh_in, float* sh_w) {
    const int tid  = threadIdx.x;
    const int lb   = tid & 63, seg = tid >> 6;        // input loader mapping
    const int wn   = (tid & 15) << 2, wk = tid >> 4;  // weight loader mapping
    const int tcol = tid & 15, trow = tid >> 4;       // compute mapping

    unsigned long long acc[2][4];
#pragma unroll
    for (int q = 0; q < 4; ++q) {
        float bq = bias[n0 + (tcol << 2) + q];
        acc[0][q] = packdup(bq);
        acc[1][q] = acc[0][q];
    }

    const float* s1row = src1 + (size_t)(bBase + lb) * rs1;
    const float* s2row = src2 + (size_t)(bBase + lb) * H_;

    for (int k0 = 0; k0 < KSZ; k0 += KS) {
        // stage input tile [KS][MT] (transposed, conflict-free: bank = lb%32)
#pragma unroll
        for (int hh = 0; hh < 2; ++hh) {
            int kl = seg * 8 + hh * 4;
            int kg = k0 + kl;
            float4 v = (kg < LEN1) ? *(const float4*)(s1row + kg)
                                   : *(const float4*)(s2row + (kg - LEN1));
            float* dptr = sh_in + kl * MT + lb;
            dptr[0 * MT] = v.x; dptr[1 * MT] = v.y;
            dptr[2 * MT] = v.z; dptr[3 * MT] = v.w;
        }
        // stage weight tile [KS][NT] (weights prepacked k-major -> coalesced)
#pragma unroll
        for (int hh = 0; hh < 2; ++hh) {
            int kl = wk + hh * 16;
            *(float4*)(sh_w + kl * NT + wn) =
                *(const float4*)(Wt + (size_t)(k0 + kl) * G_ + n0 + wn);
        }
        __syncthreads();
#pragma unroll
        for (int k = 0; k < KS; ++k) {
            ulonglong2 hp = *(const ulonglong2*)(sh_in + k * MT + (trow << 2));
            float4 wv = *(const float4*)(sh_w + k * NT + (tcol << 2));
            unsigned long long w0 = packdup(wv.x), w1 = packdup(wv.y);
            unsigned long long w2 = packdup(wv.z), w3 = packdup(wv.w);
            ffma2(acc[0][0], hp.x, w0); ffma2(acc[1][0], hp.y, w0);
            ffma2(acc[0][1], hp.x, w1); ffma2(acc[1][1], hp.y, w1);
            ffma2(acc[0][2], hp.x, w2); ffma2(acc[1][2], hp.y, w2);
            ffma2(acc[0][3], hp.x, w3); ffma2(acc[1][3], hp.y, w3);
        }
        __syncthreads();
    }

    // LSTM cell epilogue: thread owns 4 batch rows x 1 h-col (all 4 gates)
#pragma unroll
    for (int p = 0; p < 2; ++p) {
        float2 gi = unpack2(acc[p][0]);
        float2 gf = unpack2(acc[p][1]);
        float2 gg = unpack2(acc[p][2]);
        float2 go = unpack2(acc[p][3]);
#pragma unroll
        for (int e = 0; e < 2; ++e) {
            int b = bBase + (trow << 2) + (p << 1) + e;
            float iv = e ? gi.y : gi.x;
            float fv = e ? gf.y : gf.x;
            float gv = e ? gg.y : gg.x;
            float ov = e ? go.y : go.x;
            size_t idx = (size_t)b * H_ + jcol0 + tcol;
            float c  = cSt[idx];
            float cn = sigm(fv) * c + sigm(iv) * tanhf(gv);
            cSt[idx] = cn;
            hOut[idx] = sigm(ov) * tanhf(cn);
        }
    }
}

// ---------------- persistent main kernel -------------------------------------
// CTAs [0,64): layer0 of step t=phase ; CTAs [64,128): layer1 of step t=phase-1.
// One software grid barrier per phase; h-state double-buffered by t parity.
__global__ void __launch_bounds__(256, 1) lstm_main(const float* __restrict__ x) {
    __shared__ __align__(16) float sh_in[KS * MT];
    __shared__ __align__(16) float sh_w[KS * NT];

    const int cta = blockIdx.x, tid = threadIdx.x;
    unsigned relBase = *(volatile unsigned*)&g_release;   // graph-replay safe base
    unsigned gen = 0;

    // zero all state each launch (deterministic)
    for (int i = cta * 256 + tid; i < 6 * BH; i += NCTA * 256) g_state[i] = 0.f;
    gridBarrier(relBase + ++gen);

    const bool isL1 = (cta >= L0_CTAS);
    const int lc    = isL1 ? (cta - L0_CTAS) : cta;
    const int bBase = (lc >> 5) * MT;    // 2 batch tiles
    const int n0    = (lc & 31) * NT;    // 32 gate-col tiles
    const int jcol0 = n0 >> 2;

    float* h0b0 = g_state;
    float* h0b1 = g_state + BH;
    float* h1b0 = g_state + 2 * BH;
    float* h1b1 = g_state + 3 * BH;
    float* c0   = g_state + 4 * BH;
    float* c1   = g_state + 5 * BH;

    for (int phase = 0; phase <= T_; ++phase) {
        if (!isL1) {
            if (phase < T_) {
                int t = phase;
                const float* hprev = (t & 1) ? h0b0 : h0b1;   // h0(t-1)
                float* hout        = (t & 1) ? h0b1 : h0b0;   // h0(t)
                lstm_tile<K0_, D_>(g_W0T, g_b0,
                                   x + (size_t)t * D_, T_ * D_,  // x[b][t][:] rows
                                   hprev, c0, hout,
                                   bBase, n0, jcol0, sh_in, sh_w);
            }
        } else {
            if (phase >= 1) {
                int t = phase - 1;
                const float* h0cur  = (t & 1) ? h0b1 : h0b0;  // h0(t)
                const float* h1prev = (t & 1) ? h1b0 : h1b1;  // h1(t-1)
                float* hout         = (t & 1) ? h1b1 : h1b0;  // h1(t)
                lstm_tile<K1_, H_>(g_W1T, g_b1,
                                   h0cur, H_, h1prev, c1, hout,
                                   bBase, n0, jcol0, sh_in, sh_w);
            }
        }
        gridBarrier(relBase + ++gen);
    }
}

// ---------------- FC head -----------------------------------------------------
// out[b] = relu(h1 @ fc1_w.T + fc1_b) @ fc2_w.T + fc2_b ; final h1 = buf1.
__global__ void fc_head(const float* __restrict__ fc1w, const float* __restrict__ fc1b,
                        const float* __restrict__ fc2w, const float* __restrict__ fc2b,
                        float* __restrict__ out) {
    int b = blockIdx.x;
    int j = threadIdx.x;  // 32 hidden units
    const float* h = g_state + 3 * BH + (size_t)b * H_;
    const float* w = fc1w + (size_t)j * H_;
    float s = fc1b[j];
    for (int k = 0; k < H_; ++k) s += h[k] * w[k];
    float r = fmaxf(s, 0.f) * fc2w[j];
#pragma unroll
    for (int off = 16; off; off >>= 1) r += __shfl_xor_sync(0xffffffffu, r, off);
    if (j == 0) out[b] = r + fc2b[0];
}

// ---------------- launch ------------------------------------------------------
extern "C" void kernel_launch(void* const* d_in, const int* in_sizes, int n_in,
                              void* d_out, int out_size) {
    const float* x     = (const float*)d_in[0];
    const float* projw = (const float*)d_in[1];
    const float* projb = (const float*)d_in[2];
    const float* wx0   = (const float*)d_in[3];
    const float* bx0   = (const float*)d_in[4];
    const float* wh0   = (const float*)d_in[5];
    const float* bh0   = (const float*)d_in[6];
    const float* wx1   = (const float*)d_in[7];
    const float* bx1   = (const float*)d_in[8];
    const float* wh1   = (const float*)d_in[9];
    const float* bh1   = (const float*)d_in[10];
    const float* fc1w  = (const float*)d_in[11];
    const float* fc1b  = (const float*)d_in[12];
    const float* fc2w  = (const float*)d_in[13];
    const float* fc2b  = (const float*)d_in[14];
    float* out = (float*)d_out;

    prep_w0<<<G_, D_>>>(wx0, projw, projb, bx0, bh0);
    prep_copy<<<1024, 256>>>(wh0, wx1, wh1, bx1, bh1);
    lstm_main<<<NCTA, 256>>>(x);
    fc_head<<<B_, 32>>>(fc1w, fc1b, fc2w, fc2b, out);
}

// round 2
// speedup vs baseline: 1.3445x; 1.3445x over previous
#include <cuda_runtime.h>
#include <cstdint>

// Problem constants
#define B_   128
#define T_   512
#define D_   256
#define H_   512
#define G_   2048          // 4*H
#define K0_  768           // D + H (layer0 concat K)
#define K1_  1024          // H + H (layer1 concat K)
#define NCTA 128
#define BH   (B_ * H_)

// ---------------- persistent device scratch ----------------------------------
__device__ float g_W0T[(size_t)K0_ * G_];   // [k][n'] k-major, gate-interleaved, proj folded
__device__ float g_W1T[(size_t)K1_ * G_];
__device__ float g_b0[G_];
__device__ float g_b1[G_];
// h state double buffers: h0b0, h0b1, h1b0, h1b1
__device__ float g_state[4 * BH];
__device__ unsigned g_count;
__device__ unsigned g_release;

// ---------------- helpers ----------------------------------------------------
__device__ __forceinline__ unsigned long long packdup(float w) {
    unsigned long long r;
    unsigned u = __float_as_uint(w);
    asm("mov.b64 %0, {%1, %1};" : "=l"(r) : "r"(u));
    return r;
}
__device__ __forceinline__ void ffma2(unsigned long long& d,
                                      unsigned long long a,
                                      unsigned long long b) {
    asm("fma.rn.f32x2 %0, %1, %2, %0;" : "+l"(d) : "l"(a), "l"(b));
}
__device__ __forceinline__ float2 unpack2(unsigned long long v) {
    unsigned lo, hi;
    asm("mov.b64 {%0, %1}, %2;" : "=r"(lo), "=r"(hi) : "l"(v));
    return make_float2(__uint_as_float(lo), __uint_as_float(hi));
}
__device__ __forceinline__ float sigm(float v) { return 1.f / (1.f + __expf(-v)); }

// swizzled offset into [64][128] staged input tile: row k, col b (b low 2 bits free)
__device__ __forceinline__ int swz(int k, int b) {
    return (k << 7) + (b ^ (((k >> 2) & 7) << 2));
}

__device__ __forceinline__ void gridBarrier(unsigned target) {
    __syncthreads();
    if (threadIdx.x == 0) {
        __threadfence();
        unsigned t = atomicAdd(&g_count, 1u);
        if (t == (unsigned)(NCTA - 1)) {
            g_count = 0;
            __threadfence();
            atomicAdd(&g_release, 1u);
        } else {
            while ((int)(*(volatile unsigned*)&g_release - target) < 0) {}
        }
        __threadfence();
    }
    __syncthreads();
}

// ---------------- weight preparation (unchanged from R1, validated) ----------
__global__ void prep_w0(const float* __restrict__ wx0, const float* __restrict__ projw,
                        const float* __restrict__ projb, const float* __restrict__ bx0,
                        const float* __restrict__ bh0) {
    int np = blockIdx.x;                 // n'
    int jcol = np >> 2, q = np & 3;
    int n = q * H_ + jcol;
    int d = threadIdx.x;                 // 0..255
    const float* wrow = wx0 + (size_t)n * D_;
    float acc = 0.f;
    for (int j = 0; j < D_; ++j) acc += wrow[j] * projw[(size_t)j * D_ + d];
    g_W0T[(size_t)d * G_ + np] = acc;
    if (d == 0) {
        float bb = bx0[n] + bh0[n];
        for (int j = 0; j < D_; ++j) bb += wrow[j] * projb[j];
        g_b0[np] = bb;
    }
}

__global__ void prep_copy(const float* __restrict__ wh0, const float* __restrict__ wx1,
                          const float* __restrict__ wh1, const float* __restrict__ bx1,
                          const float* __restrict__ bh1) {
    const int total = H_ * G_ + K1_ * G_ + G_;
    for (int i = blockIdx.x * blockDim.x + threadIdx.x; i < total;
         i += gridDim.x * blockDim.x) {
        if (i < H_ * G_) {
            int k = i / G_, np = i % G_;
            int n = (np & 3) * H_ + (np >> 2);
            g_W0T[(size_t)(D_ + k) * G_ + np] = wh0[(size_t)n * H_ + k];
        } else if (i < H_ * G_ + K1_ * G_) {
            int r = i - H_ * G_;
            int k = r / G_, np = r % G_;
            int n = (np & 3) * H_ + (np >> 2);
            float v = (k < H_) ? wx1[(size_t)n * H_ + k] : wh1[(size_t)n * H_ + (k - H_)];
            g_W1T[(size_t)k * G_ + np] = v;
        } else {
            int np = i - H_ * G_ - K1_ * G_;
            int n = (np & 3) * H_ + (np >> 2);
            g_b1[np] = bx1[n] + bh1[n];
        }
    }
}

// ---------------- slice primitives --------------------------------------------
// LDG a 64-k x 128-b input slice into registers (k-contiguous per thread: coalesced)
template <int LEN1>
__device__ __forceinline__ void ldg_slice(float4 (&r)[8], int s,
    const float* __restrict__ src1, int st1, const float* __restrict__ src2,
    int kc, int sb) {
    int k0 = s * 64;
    const float* src; int st;
    if (k0 < LEN1) { src = src1 + k0; st = st1; }
    else           { src = src2 + (k0 - LEN1); st = H_; }
    const float* p = src + (kc << 2) + (size_t)sb * st;
#pragma unroll
    for (int rr = 0; rr < 8; ++rr)
        r[rr] = *(const float4*)(p + (size_t)rr * 16 * st);
}

// transpose-store regs into swizzled smem tile (2-way max bank conflict)
__device__ __forceinline__ void sts_slice(float* __restrict__ buf,
                                          const float4 (&r)[8], int kc, int sb) {
    int kl = kc << 2;
#pragma unroll
    for (int rr = 0; rr < 8; ++rr) {
        int b = sb + (rr << 4);
        buf[swz(kl + 0, b)] = r[rr].x;
        buf[swz(kl + 1, b)] = r[rr].y;
        buf[swz(kl + 2, b)] = r[rr].z;
        buf[swz(kl + 3, b)] = r[rr].w;
    }
}

// 64-k compute: 16 outputs/thread (4 batch x 4 gates) as 8 f32x2 accumulators
__device__ __forceinline__ void comp_slice(unsigned long long (&acc)[2][4],
    const float* __restrict__ buf, const float* __restrict__ wk, int trow4) {
#pragma unroll 16
    for (int k = 0; k < 64; ++k) {
        ulonglong2 hp = *(const ulonglong2*)(buf + swz(k, trow4));
        float4 wv = *(const float4*)(wk + (k << 5));
        unsigned long long w0 = packdup(wv.x), w1 = packdup(wv.y);
        unsigned long long w2 = packdup(wv.z), w3 = packdup(wv.w);
        ffma2(acc[0][0], hp.x, w0); ffma2(acc[1][0], hp.y, w0);
        ffma2(acc[0][1], hp.x, w1); ffma2(acc[1][1], hp.y, w1);
        ffma2(acc[0][2], hp.x, w2); ffma2(acc[1][2], hp.y, w2);
        ffma2(acc[0][3], hp.x, w3); ffma2(acc[1][3], hp.y, w3);
    }
}

// ---------------- one LSTM layer step (GEMM + cell epilogue) ------------------
// tile: [128 batch x 32 gate-cols], weights resident in sh_w, c in registers.
template <int KSZ, int LEN1>
__device__ void lstm_phase(const float* __restrict__ sh_w,
    float* __restrict__ bufA, float* __restrict__ bufB,
    const float* __restrict__ src1, int st1, const float* __restrict__ src2,
    float* __restrict__ hOut, float* __restrict__ cc,
    float4 bias, int jcol0) {
    const int tid = threadIdx.x;
    const int tcol = tid & 7, trow4 = (tid >> 3) << 2;
    const int kc = tid & 15, sb = tid >> 4;

    unsigned long long acc[2][4];
    acc[0][0] = packdup(bias.x); acc[0][1] = packdup(bias.y);
    acc[0][2] = packdup(bias.z); acc[0][3] = packdup(bias.w);
#pragma unroll
    for (int q = 0; q < 4; ++q) acc[1][q] = acc[0][q];

    constexpr int NS = KSZ / 64;
    float4 r[8];
    ldg_slice<LEN1>(r, 0, src1, st1, src2, kc, sb);
    sts_slice(bufA, r, kc, sb);
    __syncthreads();

#pragma unroll 1
    for (int s = 0; s < NS; ++s) {
        if (s + 1 < NS) ldg_slice<LEN1>(r, s + 1, src1, st1, src2, kc, sb);
        comp_slice(acc, (s & 1) ? bufB : bufA,
                   sh_w + s * 64 * 32 + (tcol << 2), trow4);
        __syncthreads();
        if (s + 1 < NS) {
            sts_slice(((s + 1) & 1) ? bufB : bufA, r, kc, sb);
            __syncthreads();
        }
    }

    // LSTM cell epilogue: 4 cells/thread, c in registers
#pragma unroll
    for (int p = 0; p < 2; ++p) {
        float2 gi = unpack2(acc[p][0]);
        float2 gf = unpack2(acc[p][1]);
        float2 gg = unpack2(acc[p][2]);
        float2 go = unpack2(acc[p][3]);
#pragma unroll
        for (int e = 0; e < 2; ++e) {
            int bi = (p << 1) + e;
            float iv = e ? gi.y : gi.x, fv = e ? gf.y : gf.x;
            float gv = e ? gg.y : gg.x, ov = e ? go.y : go.x;
            float cn = sigm(fv) * cc[bi] + sigm(iv) * tanhf(gv);
            cc[bi] = cn;
            hOut[(size_t)(trow4 + bi) * H_ + jcol0 + tcol] = sigm(ov) * tanhf(cn);
        }
    }
}

// ---------------- persistent main kernel --------------------------------------
// CTAs [0,64): layer0 step t=phase ; CTAs [64,128): layer1 step t=phase-1.
// Weights smem-resident for the whole kernel; one grid barrier per phase.
__global__ void __launch_bounds__(256, 1) lstm_main(const float* __restrict__ x) {
    extern __shared__ float smem[];
    float* sh_w = smem;                     // up to 1024 x 32 floats (128 KB)
    float* bufA = smem + 1024 * 32;         // 64 x 128 (32 KB)
    float* bufB = bufA + 64 * 128;          // 64 x 128 (32 KB)

    const int cta = blockIdx.x, tid = threadIdx.x;
    unsigned relBase = *(volatile unsigned*)&g_release;
    unsigned gen = 0;

    const bool isL1 = (cta >= 64);
    const int lc = isL1 ? cta - 64 : cta;
    const int n0 = lc * 32;
    const int jcol0 = lc * 8;

    // load resident weight tile (once per kernel)
    const float* gW = isL1 ? g_W1T : g_W0T;
    const int Kk = isL1 ? K1_ : K0_;
    for (int i = tid; i < Kk * 8; i += 256) {
        int k = i >> 3, c2 = (i & 7) << 2;
        *(float4*)(sh_w + k * 32 + c2) = *(const float4*)(gW + (size_t)k * G_ + n0 + c2);
    }
    const float* gb = isL1 ? g_b1 : g_b0;
    float4 bias = *(const float4*)(gb + n0 + ((tid & 7) << 2));

    // zero h buffers each launch (deterministic)
    for (int i = cta * 256 + tid; i < 4 * BH; i += NCTA * 256) g_state[i] = 0.f;

    float cc[4] = {0.f, 0.f, 0.f, 0.f};   // register-resident cell state

    gridBarrier(relBase + ++gen);

    float* h0b0 = g_state;
    float* h0b1 = g_state + BH;
    float* h1b0 = g_state + 2 * BH;
    float* h1b1 = g_state + 3 * BH;

    for (int phase = 0; phase <= T_; ++phase) {
        if (!isL1) {
            if (phase < T_) {
                int t = phase;
                const float* hprev = (t & 1) ? h0b0 : h0b1;   // h0(t-1)
                float* hout        = (t & 1) ? h0b1 : h0b0;   // h0(t)
                lstm_phase<K0_, D_>(sh_w, bufA, bufB,
                                    x + (size_t)t * D_, T_ * D_,
                                    hprev, hout, cc, bias, jcol0);
            }
        } else {
            if (phase >= 1) {
                int t = phase - 1;
                const float* h0cur  = (t & 1) ? h0b1 : h0b0;  // h0(t)
                const float* h1prev = (t & 1) ? h1b0 : h1b1;  // h1(t-1)
                float* hout         = (t & 1) ? h1b1 : h1b0;  // h1(t)
                lstm_phase<K1_, H_>(sh_w, bufA, bufB,
                                    h0cur, H_, h1prev, hout, cc, bias, jcol0);
            }
        }
        gridBarrier(relBase + ++gen);
    }
}

// ---------------- FC head ------------------------------------------------------
__global__ void fc_head(const float* __restrict__ fc1w, const float* __restrict__ fc1b,
                        const float* __restrict__ fc2w, const float* __restrict__ fc2b,
                        float* __restrict__ out) {
    __shared__ float hsh[H_];
    __shared__ float hid[32];
    int b = blockIdx.x, tid = threadIdx.x;  // 256 threads
    const float* h = g_state + 3 * BH + (size_t)b * H_;  // final h1 (t=511 odd -> buf1)
    hsh[tid] = h[tid];
    hsh[tid + 256] = h[tid + 256];
    __syncthreads();
    int w = tid >> 5, lane = tid & 31;
    for (int j = w; j < 32; j += 8) {
        const float* wr = fc1w + (size_t)j * H_;
        float s = 0.f;
        for (int k = lane; k < H_; k += 32) s += hsh[k] * wr[k];
#pragma unroll
        for (int off = 16; off; off >>= 1) s += __shfl_xor_sync(0xffffffffu, s, off);
        if (lane == 0) hid[j] = fmaxf(s + fc1b[j], 0.f) * fc2w[j];
    }
    __syncthreads();
    if (tid < 32) {
        float v = hid[tid];
#pragma unroll
        for (int off = 16; off; off >>= 1) v += __shfl_xor_sync(0xffffffffu, v, off);
        if (tid == 0) out[b] = v + fc2b[0];
    }
}

// ---------------- launch --------------------------------------------------------
extern "C" void kernel_launch(void* const* d_in, const int* in_sizes, int n_in,
                              void* d_out, int out_size) {
    const float* x     = (const float*)d_in[0];
    const float* projw = (const float*)d_in[1];
    const float* projb = (const float*)d_in[2];
    const float* wx0   = (const float*)d_in[3];
    const float* bx0   = (const float*)d_in[4];
    const float* wh0   = (const float*)d_in[5];
    const float* bh0   = (const float*)d_in[6];
    const float* wx1   = (const float*)d_in[7];
    const float* bx1   = (const float*)d_in[8];
    const float* wh1   = (const float*)d_in[9];
    const float* bh1   = (const float*)d_in[10];
    const float* fc1w  = (const float*)d_in[11];
    const float* fc1b  = (const float*)d_in[12];
    const float* fc2w  = (const float*)d_in[13];
    const float* fc2b  = (const float*)d_in[14];
    float* out = (float*)d_out;

    const int SMEM_BYTES = (1024 * 32 + 2 * 64 * 128) * 4;  // 196608
    cudaFuncSetAttribute(lstm_main, cudaFuncAttributeMaxDynamicSharedMemorySize,
                         SMEM_BYTES);

    prep_w0<<<G_, D_>>>(wx0, projw, projb, bx0, bh0);
    prep_copy<<<1024, 256>>>(wh0, wx1, wh1, bx1, bh1);
    lstm_main<<<NCTA, 256, SMEM_BYTES>>>(x);
    fc_head<<<B_, 256>>>(fc1w, fc1b, fc2w, fc2b, out);
}

// round 3
// speedup vs baseline: 1.3459x; 1.0011x over previous
#include <cuda_runtime.h>
#include <cstdint>

// Problem constants
#define B_   128
#define T_   512
#define D_   256
#define H_   512
#define G_   2048          // 4*H
#define K0_  768           // D + H (layer0 concat K)
#define K1_  1024          // H + H (layer1 concat K)
#define NCTA 128
#define BH   (B_ * H_)

// ---------------- persistent device scratch ----------------------------------
__device__ float g_W0T[(size_t)K0_ * G_];   // [k][n'] k-major, gate-interleaved, proj folded
__device__ float g_W1T[(size_t)K1_ * G_];
__device__ float g_b0[G_];
__device__ float g_b1[G_];
// h state double buffers: h0b0, h0b1, h1b0, h1b1
__device__ float g_state[4 * BH];
__device__ unsigned g_count;
__device__ unsigned g_release;

// ---------------- helpers ----------------------------------------------------
__device__ __forceinline__ unsigned long long packdup(float w) {
    unsigned long long r;
    unsigned u = __float_as_uint(w);
    asm("mov.b64 %0, {%1, %1};" : "=l"(r) : "r"(u));
    return r;
}
__device__ __forceinline__ void ffma2(unsigned long long& d,
                                      unsigned long long a,
                                      unsigned long long b) {
    asm("fma.rn.f32x2 %0, %1, %2, %0;" : "+l"(d) : "l"(a), "l"(b));
}
__device__ __forceinline__ float2 unpack2(unsigned long long v) {
    unsigned lo, hi;
    asm("mov.b64 {%0, %1}, %2;" : "=r"(lo), "=r"(hi) : "l"(v));
    return make_float2(__uint_as_float(lo), __uint_as_float(hi));
}
__device__ __forceinline__ float sigm(float v) { return 1.f / (1.f + __expf(-v)); }

// swizzled offset into [64][128] staged input tile: row k, col b (b low 2 bits free)
__device__ __forceinline__ int swz(int k, int b) {
    return (k << 7) + (b ^ (((k >> 2) & 7) << 2));
}

__device__ __forceinline__ void gridBarrier(unsigned target) {
    __syncthreads();
    if (threadIdx.x == 0) {
        __threadfence();
        unsigned t = atomicAdd(&g_count, 1u);
        if (t == (unsigned)(NCTA - 1)) {
            g_count = 0;
            __threadfence();
            atomicAdd(&g_release, 1u);
        } else {
            while ((int)(*(volatile unsigned*)&g_release - target) < 0) {}
        }
        __threadfence();
    }
    __syncthreads();
}

// ---------------- weight preparation (unchanged from R1, validated) ----------
__global__ void prep_w0(const float* __restrict__ wx0, const float* __restrict__ projw,
                        const float* __restrict__ projb, const float* __restrict__ bx0,
                        const float* __restrict__ bh0) {
    int np = blockIdx.x;                 // n'
    int jcol = np >> 2, q = np & 3;
    int n = q * H_ + jcol;
    int d = threadIdx.x;                 // 0..255
    const float* wrow = wx0 + (size_t)n * D_;
    float acc = 0.f;
    for (int j = 0; j < D_; ++j) acc += wrow[j] * projw[(size_t)j * D_ + d];
    g_W0T[(size_t)d * G_ + np] = acc;
    if (d == 0) {
        float bb = bx0[n] + bh0[n];
        for (int j = 0; j < D_; ++j) bb += wrow[j] * projb[j];
        g_b0[np] = bb;
    }
}

__global__ void prep_copy(const float* __restrict__ wh0, const float* __restrict__ wx1,
                          const float* __restrict__ wh1, const float* __restrict__ bx1,
                          const float* __restrict__ bh1) {
    const int total = H_ * G_ + K1_ * G_ + G_;
    for (int i = blockIdx.x * blockDim.x + threadIdx.x; i < total;
         i += gridDim.x * blockDim.x) {
        if (i < H_ * G_) {
            int k = i / G_, np = i % G_;
            int n = (np & 3) * H_ + (np >> 2);
            g_W0T[(size_t)(D_ + k) * G_ + np] = wh0[(size_t)n * H_ + k];
        } else if (i < H_ * G_ + K1_ * G_) {
            int r = i - H_ * G_;
            int k = r / G_, np = r % G_;
            int n = (np & 3) * H_ + (np >> 2);
            float v = (k < H_) ? wx1[(size_t)n * H_ + k] : wh1[(size_t)n * H_ + (k - H_)];
            g_W1T[(size_t)k * G_ + np] = v;
        } else {
            int np = i - H_ * G_ - K1_ * G_;
            int n = (np & 3) * H_ + (np >> 2);
            g_b1[np] = bx1[n] + bh1[n];
        }
    }
}

// ---------------- slice primitives --------------------------------------------
// LDG a 64-k x 128-b input slice into registers (k-contiguous per thread: coalesced)
template <int LEN1>
__device__ __forceinline__ void ldg_slice(float4 (&r)[8], int s,
    const float* __restrict__ src1, int st1, const float* __restrict__ src2,
    int kc, int sb) {
    int k0 = s * 64;
    const float* src; int st;
    if (k0 < LEN1) { src = src1 + k0; st = st1; }
    else           { src = src2 + (k0 - LEN1); st = H_; }
    const float* p = src + (kc << 2) + (size_t)sb * st;
#pragma unroll
    for (int rr = 0; rr < 8; ++rr)
        r[rr] = *(const float4*)(p + (size_t)rr * 16 * st);
}

// transpose-store regs into swizzled smem tile (2-way max bank conflict)
__device__ __forceinline__ void sts_slice(float* __restrict__ buf,
                                          const float4 (&r)[8], int kc, int sb) {
    int kl = kc << 2;
#pragma unroll
    for (int rr = 0; rr < 8; ++rr) {
        int b = sb + (rr << 4);
        buf[swz(kl + 0, b)] = r[rr].x;
        buf[swz(kl + 1, b)] = r[rr].y;
        buf[swz(kl + 2, b)] = r[rr].z;
        buf[swz(kl + 3, b)] = r[rr].w;
    }
}

// 64-k compute: 16 outputs/thread (4 batch x 4 gates) as 8 f32x2 accumulators
__device__ __forceinline__ void comp_slice(unsigned long long (&acc)[2][4],
    const float* __restrict__ buf, const float* __restrict__ wk, int trow4) {
#pragma unroll 16
    for (int k = 0; k < 64; ++k) {
        ulonglong2 hp = *(const ulonglong2*)(buf + swz(k, trow4));
        float4 wv = *(const float4*)(wk + (k << 5));
        unsigned long long w0 = packdup(wv.x), w1 = packdup(wv.y);
        unsigned long long w2 = packdup(wv.z), w3 = packdup(wv.w);
        ffma2(acc[0][0], hp.x, w0); ffma2(acc[1][0], hp.y, w0);
        ffma2(acc[0][1], hp.x, w1); ffma2(acc[1][1], hp.y, w1);
        ffma2(acc[0][2], hp.x, w2); ffma2(acc[1][2], hp.y, w2);
        ffma2(acc[0][3], hp.x, w3); ffma2(acc[1][3], hp.y, w3);
    }
}

// ---------------- one LSTM layer step (GEMM + cell epilogue) ------------------
// tile: [128 batch x 32 gate-cols], weights resident in sh_w, c in registers.
template <int KSZ, int LEN1>
__device__ void lstm_phase(const float* __restrict__ sh_w,
    float* __restrict__ bufA, float* __restrict__ bufB,
    const float* __restrict__ src1, int st1, const float* __restrict__ src2,
    float* __restrict__ hOut, float* __restrict__ cc,
    float4 bias, int jcol0) {
    const int tid = threadIdx.x;
    const int tcol = tid & 7, trow4 = (tid >> 3) << 2;
    const int kc = tid & 15, sb = tid >> 4;

    unsigned long long acc[2][4];
    acc[0][0] = packdup(bias.x); acc[0][1] = packdup(bias.y);
    acc[0][2] = packdup(bias.z); acc[0][3] = packdup(bias.w);
#pragma unroll
    for (int q = 0; q < 4; ++q) acc[1][q] = acc[0][q];

    constexpr int NS = KSZ / 64;
    float4 r[8];
    ldg_slice<LEN1>(r, 0, src1, st1, src2, kc, sb);
    sts_slice(bufA, r, kc, sb);
    __syncthreads();

#pragma unroll 1
    for (int s = 0; s < NS; ++s) {
        if (s + 1 < NS) ldg_slice<LEN1>(r, s + 1, src1, st1, src2, kc, sb);
        comp_slice(acc, (s & 1) ? bufB : bufA,
                   sh_w + s * 64 * 32 + (tcol << 2), trow4);
        __syncthreads();
        if (s + 1 < NS) {
            sts_slice(((s + 1) & 1) ? bufB : bufA, r, kc, sb);
            __syncthreads();
        }
    }

    // LSTM cell epilogue: 4 cells/thread, c in registers
#pragma unroll
    for (int p = 0; p < 2; ++p) {
        float2 gi = unpack2(acc[p][0]);
        float2 gf = unpack2(acc[p][1]);
        float2 gg = unpack2(acc[p][2]);
        float2 go = unpack2(acc[p][3]);
#pragma unroll
        for (int e = 0; e < 2; ++e) {
            int bi = (p << 1) + e;
            float iv = e ? gi.y : gi.x, fv = e ? gf.y : gf.x;
            float gv = e ? gg.y : gg.x, ov = e ? go.y : go.x;
            float cn = sigm(fv) * cc[bi] + sigm(iv) * tanhf(gv);
            cc[bi] = cn;
            hOut[(size_t)(trow4 + bi) * H_ + jcol0 + tcol] = sigm(ov) * tanhf(cn);
        }
    }
}

// ---------------- persistent main kernel --------------------------------------
// CTAs [0,64): layer0 step t=phase ; CTAs [64,128): layer1 step t=phase-1.
// Weights smem-resident for the whole kernel; one grid barrier per phase.
__global__ void __launch_bounds__(256, 1) lstm_main(const float* __restrict__ x) {
    extern __shared__ float smem[];
    float* sh_w = smem;                     // up to 1024 x 32 floats (128 KB)
    float* bufA = smem + 1024 * 32;         // 64 x 128 (32 KB)
    float* bufB = bufA + 64 * 128;          // 64 x 128 (32 KB)

    const int cta = blockIdx.x, tid = threadIdx.x;
    unsigned relBase = *(volatile unsigned*)&g_release;
    unsigned gen = 0;

    const bool isL1 = (cta >= 64);
    const int lc = isL1 ? cta - 64 : cta;
    const int n0 = lc * 32;
    const int jcol0 = lc * 8;

    // load resident weight tile (once per kernel)
    const float* gW = isL1 ? g_W1T : g_W0T;
    const int Kk = isL1 ? K1_ : K0_;
    for (int i = tid; i < Kk * 8; i += 256) {
        int k = i >> 3, c2 = (i & 7) << 2;
        *(float4*)(sh_w + k * 32 + c2) = *(const float4*)(gW + (size_t)k * G_ + n0 + c2);
    }
    const float* gb = isL1 ? g_b1 : g_b0;
    float4 bias = *(const float4*)(gb + n0 + ((tid & 7) << 2));

    // zero h buffers each launch (deterministic)
    for (int i = cta * 256 + tid; i < 4 * BH; i += NCTA * 256) g_state[i] = 0.f;

    float cc[4] = {0.f, 0.f, 0.f, 0.f};   // register-resident cell state

    gridBarrier(relBase + ++gen);

    float* h0b0 = g_state;
    float* h0b1 = g_state + BH;
    float* h1b0 = g_state + 2 * BH;
    float* h1b1 = g_state + 3 * BH;

    for (int phase = 0; phase <= T_; ++phase) {
        if (!isL1) {
            if (phase < T_) {
                int t = phase;
                const float* hprev = (t & 1) ? h0b0 : h0b1;   // h0(t-1)
                float* hout        = (t & 1) ? h0b1 : h0b0;   // h0(t)
                lstm_phase<K0_, D_>(sh_w, bufA, bufB,
                                    x + (size_t)t * D_, T_ * D_,
                                    hprev, hout, cc, bias, jcol0);
            }
        } else {
            if (phase >= 1) {
                int t = phase - 1;
                const float* h0cur  = (t & 1) ? h0b1 : h0b0;  // h0(t)
                const float* h1prev = (t & 1) ? h1b0 : h1b1;  // h1(t-1)
                float* hout         = (t & 1) ? h1b1 : h1b0;  // h1(t)
                lstm_phase<K1_, H_>(sh_w, bufA, bufB,
                                    h0cur, H_, h1prev, hout, cc, bias, jcol0);
            }
        }
        gridBarrier(relBase + ++gen);
    }
}

// ---------------- FC head ------------------------------------------------------
__global__ void fc_head(const float* __restrict__ fc1w, const float* __restrict__ fc1b,
                        const float* __restrict__ fc2w, const float* __restrict__ fc2b,
                        float* __restrict__ out) {
    __shared__ float hsh[H_];
    __shared__ float hid[32];
    int b = blockIdx.x, tid = threadIdx.x;  // 256 threads
    const float* h = g_state + 3 * BH + (size_t)b * H_;  // final h1 (t=511 odd -> buf1)
    hsh[tid] = h[tid];
    hsh[tid + 256] = h[tid + 256];
    __syncthreads();
    int w = tid >> 5, lane = tid & 31;
    for (int j = w; j < 32; j += 8) {
        const float* wr = fc1w + (size_t)j * H_;
        float s = 0.f;
        for (int k = lane; k < H_; k += 32) s += hsh[k] * wr[k];
#pragma unroll
        for (int off = 16; off; off >>= 1) s += __shfl_xor_sync(0xffffffffu, s, off);
        if (lane == 0) hid[j] = fmaxf(s + fc1b[j], 0.f) * fc2w[j];
    }
    __syncthreads();
    if (tid < 32) {
        float v = hid[tid];
#pragma unroll
        for (int off = 16; off; off >>= 1) v += __shfl_xor_sync(0xffffffffu, v, off);
        if (tid == 0) out[b] = v + fc2b[0];
    }
}

// ---------------- launch --------------------------------------------------------
extern "C" void kernel_launch(void* const* d_in, const int* in_sizes, int n_in,
                              void* d_out, int out_size) {
    const float* x     = (const float*)d_in[0];
    const float* projw = (const float*)d_in[1];
    const float* projb = (const float*)d_in[2];
    const float* wx0   = (const float*)d_in[3];
    const float* bx0   = (const float*)d_in[4];
    const float* wh0   = (const float*)d_in[5];
    const float* bh0   = (const float*)d_in[6];
    const float* wx1   = (const float*)d_in[7];
    const float* bx1   = (const float*)d_in[8];
    const float* wh1   = (const float*)d_in[9];
    const float* bh1   = (const float*)d_in[10];
    const float* fc1w  = (const float*)d_in[11];
    const float* fc1b  = (const float*)d_in[12];
    const float* fc2w  = (const float*)d_in[13];
    const float* fc2b  = (const float*)d_in[14];
    float* out = (float*)d_out;

    const int SMEM_BYTES = (1024 * 32 + 2 * 64 * 128) * 4;  // 196608
    cudaFuncSetAttribute(lstm_main, cudaFuncAttributeMaxDynamicSharedMemorySize,
                         SMEM_BYTES);

    prep_w0<<<G_, D_>>>(wx0, projw, projb, bx0, bh0);
    prep_copy<<<1024, 256>>>(wh0, wx1, wh1, bx1, bh1);
    lstm_main<<<NCTA, 256, SMEM_BYTES>>>(x);
    fc_head<<<B_, 256>>>(fc1w, fc1b, fc2w, fc2b, out);
}

// round 4
// speedup vs baseline: 1.3648x; 1.0140x over previous
#include <cuda_runtime.h>
#include <cstdint>

// Problem constants
#define B_   128
#define T_   512
#define D_   256
#define H_   512
#define G_   2048          // 4*H
#define K0_  768           // D + H (layer0 concat K)
#define K1_  1024          // H + H (layer1 concat K)
#define NCTA 128
#define BH   (B_ * H_)

// ---------------- persistent device scratch ----------------------------------
__device__ float g_W0T[(size_t)K0_ * G_];   // [k][n'] k-major, gate-interleaved, proj folded
__device__ float g_W1T[(size_t)K1_ * G_];
__device__ float g_b0[G_];
__device__ float g_b1[G_];
// h state double buffers: h0b0, h0b1, h1b0, h1b1
__device__ float g_state[4 * BH];
__device__ unsigned g_count;
__device__ unsigned g_release;

// ---------------- helpers ----------------------------------------------------
__device__ __forceinline__ unsigned long long packdup(float w) {
    unsigned long long r;
    unsigned u = __float_as_uint(w);
    asm("mov.b64 %0, {%1, %1};" : "=l"(r) : "r"(u));
    return r;
}
__device__ __forceinline__ void ffma2(unsigned long long& d,
                                      unsigned long long a,
                                      unsigned long long b) {
    asm("fma.rn.f32x2 %0, %1, %2, %0;" : "+l"(d) : "l"(a), "l"(b));
}
__device__ __forceinline__ float2 unpack2(unsigned long long v) {
    unsigned lo, hi;
    asm("mov.b64 {%0, %1}, %2;" : "=r"(lo), "=r"(hi) : "l"(v));
    return make_float2(__uint_as_float(lo), __uint_as_float(hi));
}
__device__ __forceinline__ float sigm(float v) { return 1.f / (1.f + __expf(-v)); }

// swizzled offset into [64][128] staged input tile: row k, col b (b low 2 bits free)
__device__ __forceinline__ int swz(int k, int b) {
    return (k << 7) + (b ^ (((k >> 2) & 7) << 2));
}

__device__ __forceinline__ void gridBarrier(unsigned target) {
    __syncthreads();
    if (threadIdx.x == 0) {
        __threadfence();
        unsigned t = atomicAdd(&g_count, 1u);
        if (t == (unsigned)(NCTA - 1)) {
            g_count = 0;
            __threadfence();
            atomicAdd(&g_release, 1u);
        } else {
            while ((int)(*(volatile unsigned*)&g_release - target) < 0) {}
        }
        __threadfence();
    }
    __syncthreads();
}

// ---------------- weight preparation (unchanged from R1, validated) ----------
__global__ void prep_w0(const float* __restrict__ wx0, const float* __restrict__ projw,
                        const float* __restrict__ projb, const float* __restrict__ bx0,
                        const float* __restrict__ bh0) {
    int np = blockIdx.x;                 // n'
    int jcol = np >> 2, q = np & 3;
    int n = q * H_ + jcol;
    int d = threadIdx.x;                 // 0..255
    const float* wrow = wx0 + (size_t)n * D_;
    float acc = 0.f;
    for (int j = 0; j < D_; ++j) acc += wrow[j] * projw[(size_t)j * D_ + d];
    g_W0T[(size_t)d * G_ + np] = acc;
    if (d == 0) {
        float bb = bx0[n] + bh0[n];
        for (int j = 0; j < D_; ++j) bb += wrow[j] * projb[j];
        g_b0[np] = bb;
    }
}

__global__ void prep_copy(const float* __restrict__ wh0, const float* __restrict__ wx1,
                          const float* __restrict__ wh1, const float* __restrict__ bx1,
                          const float* __restrict__ bh1) {
    const int total = H_ * G_ + K1_ * G_ + G_;
    for (int i = blockIdx.x * blockDim.x + threadIdx.x; i < total;
         i += gridDim.x * blockDim.x) {
        if (i < H_ * G_) {
            int k = i / G_, np = i % G_;
            int n = (np & 3) * H_ + (np >> 2);
            g_W0T[(size_t)(D_ + k) * G_ + np] = wh0[(size_t)n * H_ + k];
        } else if (i < H_ * G_ + K1_ * G_) {
            int r = i - H_ * G_;
            int k = r / G_, np = r % G_;
            int n = (np & 3) * H_ + (np >> 2);
            float v = (k < H_) ? wx1[(size_t)n * H_ + k] : wh1[(size_t)n * H_ + (k - H_)];
            g_W1T[(size_t)k * G_ + np] = v;
        } else {
            int np = i - H_ * G_ - K1_ * G_;
            int n = (np & 3) * H_ + (np >> 2);
            g_b1[np] = bx1[n] + bh1[n];
        }
    }
}

// ---------------- slice primitives --------------------------------------------
// LDG a 64-k x 128-b input slice into registers (k-contiguous per thread: coalesced)
template <int LEN1>
__device__ __forceinline__ void ldg_slice(float4 (&r)[8], int s,
    const float* __restrict__ src1, int st1, const float* __restrict__ src2,
    int kc, int sb) {
    int k0 = s * 64;
    const float* src; int st;
    if (k0 < LEN1) { src = src1 + k0; st = st1; }
    else           { src = src2 + (k0 - LEN1); st = H_; }
    const float* p = src + (kc << 2) + (size_t)sb * st;
#pragma unroll
    for (int rr = 0; rr < 8; ++rr)
        r[rr] = *(const float4*)(p + (size_t)rr * 16 * st);
}

// transpose-store regs into swizzled smem tile (2-way max bank conflict)
__device__ __forceinline__ void sts_slice(float* __restrict__ buf,
                                          const float4 (&r)[8], int kc, int sb) {
    int kl = kc << 2;
#pragma unroll
    for (int rr = 0; rr < 8; ++rr) {
        int b = sb + (rr << 4);
        buf[swz(kl + 0, b)] = r[rr].x;
        buf[swz(kl + 1, b)] = r[rr].y;
        buf[swz(kl + 2, b)] = r[rr].z;
        buf[swz(kl + 3, b)] = r[rr].w;
    }
}

// 64-k compute: 16 outputs/thread (4 batch x 4 gates) as 8 f32x2 accumulators
__device__ __forceinline__ void comp_slice(unsigned long long (&acc)[2][4],
    const float* __restrict__ buf, const float* __restrict__ wk, int trow4) {
#pragma unroll 16
    for (int k = 0; k < 64; ++k) {
        ulonglong2 hp = *(const ulonglong2*)(buf + swz(k, trow4));
        float4 wv = *(const float4*)(wk + (k << 5));
        unsigned long long w0 = packdup(wv.x), w1 = packdup(wv.y);
        unsigned long long w2 = packdup(wv.z), w3 = packdup(wv.w);
        ffma2(acc[0][0], hp.x, w0); ffma2(acc[1][0], hp.y, w0);
        ffma2(acc[0][1], hp.x, w1); ffma2(acc[1][1], hp.y, w1);
        ffma2(acc[0][2], hp.x, w2); ffma2(acc[1][2], hp.y, w2);
        ffma2(acc[0][3], hp.x, w3); ffma2(acc[1][3], hp.y, w3);
    }
}

// ---------------- one LSTM layer step (GEMM + cell epilogue) ------------------
// tile: [128 batch x 32 gate-cols], weights resident in sh_w, c in registers.
template <int KSZ, int LEN1>
__device__ void lstm_phase(const float* __restrict__ sh_w,
    float* __restrict__ bufA, float* __restrict__ bufB,
    const float* __restrict__ src1, int st1, const float* __restrict__ src2,
    float* __restrict__ hOut, float* __restrict__ cc,
    float4 bias, int jcol0) {
    const int tid = threadIdx.x;
    const int tcol = tid & 7, trow4 = (tid >> 3) << 2;
    const int kc = tid & 15, sb = tid >> 4;

    unsigned long long acc[2][4];
    acc[0][0] = packdup(bias.x); acc[0][1] = packdup(bias.y);
    acc[0][2] = packdup(bias.z); acc[0][3] = packdup(bias.w);
#pragma unroll
    for (int q = 0; q < 4; ++q) acc[1][q] = acc[0][q];

    constexpr int NS = KSZ / 64;
    float4 r[8];
    ldg_slice<LEN1>(r, 0, src1, st1, src2, kc, sb);
    sts_slice(bufA, r, kc, sb);
    __syncthreads();

#pragma unroll 1
    for (int s = 0; s < NS; ++s) {
        if (s + 1 < NS) ldg_slice<LEN1>(r, s + 1, src1, st1, src2, kc, sb);
        comp_slice(acc, (s & 1) ? bufB : bufA,
                   sh_w + s * 64 * 32 + (tcol << 2), trow4);
        __syncthreads();
        if (s + 1 < NS) {
            sts_slice(((s + 1) & 1) ? bufB : bufA, r, kc, sb);
            __syncthreads();
        }
    }

    // LSTM cell epilogue: 4 cells/thread, c in registers
#pragma unroll
    for (int p = 0; p < 2; ++p) {
        float2 gi = unpack2(acc[p][0]);
        float2 gf = unpack2(acc[p][1]);
        float2 gg = unpack2(acc[p][2]);
        float2 go = unpack2(acc[p][3]);
#pragma unroll
        for (int e = 0; e < 2; ++e) {
            int bi = (p << 1) + e;
            float iv = e ? gi.y : gi.x, fv = e ? gf.y : gf.x;
            float gv = e ? gg.y : gg.x, ov = e ? go.y : go.x;
            float cn = sigm(fv) * cc[bi] + sigm(iv) * tanhf(gv);
            cc[bi] = cn;
            hOut[(size_t)(trow4 + bi) * H_ + jcol0 + tcol] = sigm(ov) * tanhf(cn);
        }
    }
}

// ---------------- persistent main kernel --------------------------------------
// CTAs [0,64): layer0 step t=phase ; CTAs [64,128): layer1 step t=phase-1.
// Weights smem-resident for the whole kernel; one grid barrier per phase.
__global__ void __launch_bounds__(256, 1) lstm_main(const float* __restrict__ x) {
    extern __shared__ float smem[];
    float* sh_w = smem;                     // up to 1024 x 32 floats (128 KB)
    float* bufA = smem + 1024 * 32;         // 64 x 128 (32 KB)
    float* bufB = bufA + 64 * 128;          // 64 x 128 (32 KB)

    const int cta = blockIdx.x, tid = threadIdx.x;
    unsigned relBase = *(volatile unsigned*)&g_release;
    unsigned gen = 0;

    const bool isL1 = (cta >= 64);
    const int lc = isL1 ? cta - 64 : cta;
    const int n0 = lc * 32;
    const int jcol0 = lc * 8;

    // load resident weight tile (once per kernel)
    const float* gW = isL1 ? g_W1T : g_W0T;
    const int Kk = isL1 ? K1_ : K0_;
    for (int i = tid; i < Kk * 8; i += 256) {
        int k = i >> 3, c2 = (i & 7) << 2;
        *(float4*)(sh_w + k * 32 + c2) = *(const float4*)(gW + (size_t)k * G_ + n0 + c2);
    }
    const float* gb = isL1 ? g_b1 : g_b0;
    float4 bias = *(const float4*)(gb + n0 + ((tid & 7) << 2));

    // zero h buffers each launch (deterministic)
    for (int i = cta * 256 + tid; i < 4 * BH; i += NCTA * 256) g_state[i] = 0.f;

    float cc[4] = {0.f, 0.f, 0.f, 0.f};   // register-resident cell state

    gridBarrier(relBase + ++gen);

    float* h0b0 = g_state;
    float* h0b1 = g_state + BH;
    float* h1b0 = g_state + 2 * BH;
    float* h1b1 = g_state + 3 * BH;

    for (int phase = 0; phase <= T_; ++phase) {
        if (!isL1) {
            if (phase < T_) {
                int t = phase;
                const float* hprev = (t & 1) ? h0b0 : h0b1;   // h0(t-1)
                float* hout        = (t & 1) ? h0b1 : h0b0;   // h0(t)
                lstm_phase<K0_, D_>(sh_w, bufA, bufB,
                                    x + (size_t)t * D_, T_ * D_,
                                    hprev, hout, cc, bias, jcol0);
            }
        } else {
            if (phase >= 1) {
                int t = phase - 1;
                const float* h0cur  = (t & 1) ? h0b1 : h0b0;  // h0(t)
                const float* h1prev = (t & 1) ? h1b0 : h1b1;  // h1(t-1)
                float* hout         = (t & 1) ? h1b1 : h1b0;  // h1(t)
                lstm_phase<K1_, H_>(sh_w, bufA, bufB,
                                    h0cur, H_, h1prev, hout, cc, bias, jcol0);
            }
        }
        gridBarrier(relBase + ++gen);
    }
}

// ---------------- FC head ------------------------------------------------------
__global__ void fc_head(const float* __restrict__ fc1w, const float* __restrict__ fc1b,
                        const float* __restrict__ fc2w, const float* __restrict__ fc2b,
                        float* __restrict__ out) {
    __shared__ float hsh[H_];
    __shared__ float hid[32];
    int b = blockIdx.x, tid = threadIdx.x;  // 256 threads
    const float* h = g_state + 3 * BH + (size_t)b * H_;  // final h1 (t=511 odd -> buf1)
    hsh[tid] = h[tid];
    hsh[tid + 256] = h[tid + 256];
    __syncthreads();
    int w = tid >> 5, lane = tid & 31;
    for (int j = w; j < 32; j += 8) {
        const float* wr = fc1w + (size_t)j * H_;
        float s = 0.f;
        for (int k = lane; k < H_; k += 32) s += hsh[k] * wr[k];
#pragma unroll
        for (int off = 16; off; off >>= 1) s += __shfl_xor_sync(0xffffffffu, s, off);
        if (lane == 0) hid[j] = fmaxf(s + fc1b[j], 0.f) * fc2w[j];
    }
    __syncthreads();
    if (tid < 32) {
        float v = hid[tid];
#pragma unroll
        for (int off = 16; off; off >>= 1) v += __shfl_xor_sync(0xffffffffu, v, off);
        if (tid == 0) out[b] = v + fc2b[0];
    }
}

// ---------------- launch --------------------------------------------------------
extern "C" void kernel_launch(void* const* d_in, const int* in_sizes, int n_in,
                              void* d_out, int out_size) {
    const float* x     = (const float*)d_in[0];
    const float* projw = (const float*)d_in[1];
    const float* projb = (const float*)d_in[2];
    const float* wx0   = (const float*)d_in[3];
    const float* bx0   = (const float*)d_in[4];
    const float* wh0   = (const float*)d_in[5];
    const float* bh0   = (const float*)d_in[6];
    const float* wx1   = (const float*)d_in[7];
    const float* bx1   = (const float*)d_in[8];
    const float* wh1   = (const float*)d_in[9];
    const float* bh1   = (const float*)d_in[10];
    const float* fc1w  = (const float*)d_in[11];
    const float* fc1b  = (const float*)d_in[12];
    const float* fc2w  = (const float*)d_in[13];
    const float* fc2b  = (const float*)d_in[14];
    float* out = (float*)d_out;

    const int SMEM_BYTES = (1024 * 32 + 2 * 64 * 128) * 4;  // 196608
    cudaFuncSetAttribute(lstm_main, cudaFuncAttributeMaxDynamicSharedMemorySize,
                         SMEM_BYTES);

    prep_w0<<<G_, D_>>>(wx0, projw, projb, bx0, bh0);
    prep_copy<<<1024, 256>>>(wh0, wx1, wh1, bx1, bh1);
    lstm_main<<<NCTA, 256, SMEM_BYTES>>>(x);
    fc_head<<<B_, 256>>>(fc1w, fc1b, fc2w, fc2b, out);
}